// round 12
// baseline (speedup 1.0000x reference)
#include <cuda_runtime.h>
#include <cuda_bf16.h>
#include <cuda_fp16.h>
#include <stdint.h>
#include <math.h>

#define N_NODES 8192
#define NE      49152
#define ETOT    (NE + N_NODES)       // 57344
#define IN_F    128
#define H1      64
#define HID     64
#define F1      (H1*HID)             // 4096
#define H2      5
#define OUTF    32
#define F2      (H2*OUTF)            // 160
#define NB      64
#define KSPLIT  4
#define KSLC    (F1 / KSPLIT)        // 1024

// ------------------------------ scratch (static, no allocation) --------------
__device__ __half g_h1[(size_t)N_NODES * F1];                // 67 MB
__device__ __half g_x1[(size_t)N_NODES * F1];                // 67 MB
__device__ __half g_xf[N_NODES * IN_F];
__device__ __half g_w1h[F1 * IN_F];
__device__ __half g_w2h[F2 * F1];
__device__ float g_as1[N_NODES * H1];
__device__ float g_ad1[N_NODES * H1];
__device__ float g_h2p[(size_t)KSPLIT * N_NODES * F2];       // 21 MB partials
__device__ float g_h2[N_NODES * F2];
__device__ float g_as2[N_NODES * H2];
__device__ float g_ad2[N_NODES * H2];
__device__ float g_x2[N_NODES * OUTF];
__device__ int   g_counts[N_NODES];   // zero at start of every call (scan resets)
__device__ int   g_off[N_NODES + 1];
__device__ int   g_cursor[N_NODES];
__device__ int   g_csr_src[ETOT];

// ------------------------------ PTX helpers ----------------------------------
__device__ __forceinline__ uint32_t smem_u32(const void* p) {
    uint32_t a;
    asm("{ .reg .u64 t; cvta.to.shared.u64 t, %1; cvt.u32.u64 %0, t; }"
        : "=r"(a) : "l"(p));
    return a;
}

__device__ __forceinline__ void cpa16(uint32_t d, const void* s) {
    asm volatile("cp.async.cg.shared.global [%0], [%1], 16;" :: "r"(d), "l"(s));
}
__device__ __forceinline__ void cpa_commit() {
    asm volatile("cp.async.commit_group;" ::: "memory");
}
template <int N> __device__ __forceinline__ void cpa_wait() {
    asm volatile("cp.async.wait_group %0;" :: "n"(N) : "memory");
}

__device__ __forceinline__ void ldsm4(uint32_t* r, uint32_t addr) {
    asm volatile("ldmatrix.sync.aligned.m8n8.x4.shared.b16 {%0,%1,%2,%3}, [%4];"
                 : "=r"(r[0]), "=r"(r[1]), "=r"(r[2]), "=r"(r[3]) : "r"(addr));
}

__device__ __forceinline__ void mma16816h(float* c, const uint32_t* a,
                                          const uint32_t* b) {
    asm volatile(
        "mma.sync.aligned.m16n8k16.row.col.f32.f16.f16.f32 "
        "{%0,%1,%2,%3}, {%4,%5,%6,%7}, {%8,%9}, {%0,%1,%2,%3};"
        : "+f"(c[0]), "+f"(c[1]), "+f"(c[2]), "+f"(c[3])
        : "r"(a[0]), "r"(a[1]), "r"(a[2]), "r"(a[3]), "r"(b[0]), "r"(b[1]));
}

// --------- fused input conversion + edge counting ----------------------------
#define NXE (N_NODES * IN_F)     // 1048576
#define NW1 (F1 * IN_F)          // 524288
#define NW2 (F2 * F1)            // 655360
#define NSPLIT (NXE + NW1 + NW2)

__global__ void k_prep(const float* __restrict__ x, const float* __restrict__ W1,
                       const float* __restrict__ W2, const int* __restrict__ ei) {
    int i = blockIdx.x * blockDim.x + threadIdx.x;
    if (i < NE) atomicAdd(&g_counts[ei[NE + i]], 1);   // edge degree count
    if (i < NXE) {
        g_xf[i] = __float2half_rn(x[i]);
        return;
    }
    if (i < NXE + NW1) {
        int k = i - NXE;
        g_w1h[k] = __float2half_rn(W1[k]);
    } else if (i < NSPLIT) {
        int k = i - NXE - NW1;
        g_w2h[k] = __float2half_rn(W2[k]);
    }
}

// ------------------------------ CSR scan (adds self-loop, resets counts) -----
__global__ void k_scan() {
    __shared__ int sh[1024];
    int t = threadIdx.x;
    int loc[8];
    int s = 0;
#pragma unroll
    for (int j = 0; j < 8; j++) {
        int idx = t * 8 + j;
        loc[j] = g_counts[idx] + 1;    // +1 self-loop
        g_counts[idx] = 0;             // reset for next call (graph replay)
        s += loc[j];
    }
    sh[t] = s;
    __syncthreads();
    for (int off = 1; off < 1024; off <<= 1) {
        int v = (t >= off) ? sh[t - off] : 0;
        __syncthreads();
        sh[t] += v;
        __syncthreads();
    }
    int run = (t == 0) ? 0 : sh[t - 1];
#pragma unroll
    for (int j = 0; j < 8; j++) {
        int idx = t * 8 + j;
        g_off[idx] = run;
        g_cursor[idx] = run;
        run += loc[j];
    }
    if (t == 1023) g_off[N_NODES] = run;
}

__global__ void k_scatter(const int* __restrict__ ei) {
    int i = blockIdx.x * blockDim.x + threadIdx.x;
    if (i >= ETOT) return;
    int src, dst;
    if (i < NE) { src = ei[i]; dst = ei[NE + i]; }
    else        { src = i - NE; dst = src; }
    int pos = atomicAdd(&g_cursor[dst], 1);
    g_csr_src[pos] = src;
}

// ------------------------------ GEMM1 (whole-K resident + fused alpha) -------
// h1[M,4096] = xf[M,128] * W1h[4096,128]^T.  K=128 fully resident in smem.
#define T1S     272                       // bytes per smem row (17 x 16B)
#define T1TILE  (128 * T1S)               // 34816 B
#define GEMM1_SMEM (2 * T1TILE)           // 69632 B (A tile also reused as staging)

__global__ __launch_bounds__(256, 2)
void gemm1_mma(const __half* __restrict__ Af, const __half* __restrict__ Bh,
               __half* __restrict__ C,
               const float* __restrict__ att_s, const float* __restrict__ att_d) {
    extern __shared__ char smem[];
    const int N = F1, K = IN_F;
    const int tid = threadIdx.x;
    const int wid = tid >> 5, lane = tid & 31;
    const int m0 = blockIdx.y * 128, n0 = blockIdx.x * 128;
    const int wm = wid >> 1, wn = wid & 1;
    const uint32_t sb = smem_u32(smem);

    // load both whole-K tiles (A: rows m0.., B: rows n0..), 16 cp.async each thread
#pragma unroll
    for (int i = tid; i < 2048; i += 256) {
        int r = i >> 4, seg = i & 15;
        uint32_t off = (uint32_t)(r * T1S + seg * 16);
        cpa16(sb + off, Af + (size_t)(m0 + r) * K + seg * 8);
        cpa16(sb + T1TILE + off, Bh + (size_t)(n0 + r) * K + seg * 8);
    }
    cpa_commit();

    float acc[2][8][4];
#pragma unroll
    for (int im = 0; im < 2; ++im)
#pragma unroll
        for (int j = 0; j < 8; ++j)
#pragma unroll
            for (int q = 0; q < 4; ++q) acc[im][j][q] = 0.f;

    cpa_wait<0>();
    __syncthreads();

#pragma unroll
    for (int ks = 0; ks < 8; ++ks) {
        const uint32_t kb = ks * 32;      // 16 halfs = 32 B per k-step
        uint32_t a[2][4], bh[4][4];
#pragma unroll
        for (int im = 0; im < 2; ++im) {
            uint32_t ra = (uint32_t)((wm * 32 + im * 16 + (lane & 15)) * T1S)
                          + kb + ((lane >> 4) & 1) * 16;
            ldsm4(a[im], sb + ra);
        }
#pragma unroll
        for (int p = 0; p < 4; ++p) {
            uint32_t rb = (uint32_t)((wn * 64 + p * 16 + ((lane >> 4) & 1) * 8 +
                                      (lane & 7)) * T1S)
                          + kb + ((lane >> 3) & 1) * 16;
            ldsm4(bh[p], sb + T1TILE + rb);
        }
#pragma unroll
        for (int im = 0; im < 2; ++im)
#pragma unroll
            for (int j = 0; j < 8; ++j)
                mma16816h(acc[im][j], a[im], &bh[j >> 1][(j & 1) * 2]);
    }
    __syncthreads();   // tiles dead; smem becomes epilogue staging

    // epilogue 1a: stage fp16 tile into smem (row stride 68 u32 = 272 B)
    uint32_t* ep = reinterpret_cast<uint32_t*>(smem);
#pragma unroll
    for (int im = 0; im < 2; ++im)
#pragma unroll
        for (int j = 0; j < 8; ++j) {
            int r = wm * 32 + im * 16 + (lane >> 2);
            int c32 = wn * 32 + j * 4 + (lane & 3);
            __half2 v0 = __floats2half2_rn(acc[im][j][0], acc[im][j][1]);
            __half2 v1 = __floats2half2_rn(acc[im][j][2], acc[im][j][3]);
            ep[r * 68 + c32] = *reinterpret_cast<uint32_t*>(&v0);
            ep[(r + 8) * 68 + c32] = *reinterpret_cast<uint32_t*>(&v1);
        }

    // epilogue 2: fused attention dots (register-only, overlaps staging)
    const int head = (blockIdx.x << 1) + wn;
    float as_att[16], ad_att[16];
#pragma unroll
    for (int j = 0; j < 8; ++j) {
        int cc = head * HID + j * 8 + (lane & 3) * 2;
        as_att[2 * j] = att_s[cc];     as_att[2 * j + 1] = att_s[cc + 1];
        ad_att[2 * j] = att_d[cc];     ad_att[2 * j + 1] = att_d[cc + 1];
    }
#pragma unroll
    for (int im = 0; im < 2; ++im) {
        float s0 = 0.f, s1 = 0.f, d0 = 0.f, d1 = 0.f;
#pragma unroll
        for (int j = 0; j < 8; ++j) {
            s0 += acc[im][j][0] * as_att[2 * j] + acc[im][j][1] * as_att[2 * j + 1];
            s1 += acc[im][j][2] * as_att[2 * j] + acc[im][j][3] * as_att[2 * j + 1];
            d0 += acc[im][j][0] * ad_att[2 * j] + acc[im][j][1] * ad_att[2 * j + 1];
            d1 += acc[im][j][2] * ad_att[2 * j] + acc[im][j][3] * ad_att[2 * j + 1];
        }
#pragma unroll
        for (int o = 1; o < 4; o <<= 1) {
            s0 += __shfl_xor_sync(0xffffffffu, s0, o);
            s1 += __shfl_xor_sync(0xffffffffu, s1, o);
            d0 += __shfl_xor_sync(0xffffffffu, d0, o);
            d1 += __shfl_xor_sync(0xffffffffu, d1, o);
        }
        if ((lane & 3) == 0) {
            int r = m0 + wm * 32 + im * 16 + (lane >> 2);
            g_as1[r * H1 + head] = s0;
            g_ad1[r * H1 + head] = d0;
            g_as1[(r + 8) * H1 + head] = s1;
            g_ad1[(r + 8) * H1 + head] = d1;
        }
    }

    // epilogue 1b: coalesced 16B stores
    __syncthreads();
#pragma unroll
    for (int it = 0; it < 8; ++it) {
        int idx = tid + it * 256;         // 0..2047
        int row = idx >> 4, c16 = idx & 15;
        uint4 v = *reinterpret_cast<uint4*>(&ep[row * 68 + c16 * 4]);
        *reinterpret_cast<uint4*>(&C[(size_t)(m0 + row) * N + n0 + c16 * 8]) = v;
    }
}

// ------------------------------ GEMM2 (split-K x4, BN=160, 3-stage) ----------
#define TSTRIDE 80                        // bytes per smem row (5 x 16B segs)
#define A2TILE (128 * TSTRIDE)            // 10240
#define B2TILE (160 * TSTRIDE)            // 12800
#define STAGE2 (A2TILE + B2TILE)          // 23040
#define GEMM2_SMEM (3 * STAGE2)           // 69120 (also >= 64*164*4 staging)

__global__ __launch_bounds__(256, 2)
void gemm2_mma(const __half* __restrict__ Af, const __half* __restrict__ Bh,
               float* __restrict__ Cp) {
    extern __shared__ char smem[];
    const int K = F1;
    const int tid = threadIdx.x;
    const int wid = tid >> 5, lane = tid & 31;
    const int m0 = blockIdx.y * 128;
    const size_t kb0 = (size_t)blockIdx.z * KSLC;
    const int wm = wid >> 1, wn = wid & 1;
    const int NC = KSLC >> 5;             // 32
    const uint32_t sb = smem_u32(smem);

    float acc[2][10][4];
#pragma unroll
    for (int im = 0; im < 2; ++im)
#pragma unroll
        for (int j = 0; j < 10; ++j)
#pragma unroll
            for (int q = 0; q < 4; ++q) acc[im][j][q] = 0.f;

    auto load_stage = [&](int c, int s) {
        uint32_t base = sb + (uint32_t)s * STAGE2;
        const size_t kc = kb0 + (size_t)c * 32;
#pragma unroll
        for (int i = tid; i < 512; i += 256) {
            int r = i >> 2, seg = i & 3;
            uint32_t off = (uint32_t)(r * TSTRIDE + seg * 16);
            cpa16(base + off, Af + (size_t)(m0 + r) * K + kc + seg * 8);
        }
#pragma unroll
        for (int i = tid; i < 640; i += 256) {
            int r = i >> 2, seg = i & 3;
            uint32_t off = (uint32_t)(r * TSTRIDE + seg * 16);
            cpa16(base + A2TILE + off, Bh + (size_t)r * K + kc + seg * 8);
        }
        cpa_commit();
    };

    load_stage(0, 0);
    load_stage(1, 1);
    int stage = 0;
    for (int c = 0; c < NC; ++c) {
        cpa_wait<1>();
        __syncthreads();

        const uint32_t base = sb + (uint32_t)stage * STAGE2;
#pragma unroll
        for (int ks = 0; ks < 2; ++ks) {
            const uint32_t kb = ks * 32;
            uint32_t a[2][4], bh[5][4];
#pragma unroll
            for (int im = 0; im < 2; ++im) {
                uint32_t ra = (uint32_t)((wm * 32 + im * 16 + (lane & 15)) * TSTRIDE)
                              + kb + ((lane >> 4) & 1) * 16;
                ldsm4(a[im], base + ra);
            }
#pragma unroll
            for (int p = 0; p < 5; ++p) {
                uint32_t rb = (uint32_t)((wn * 80 + p * 16 + ((lane >> 4) & 1) * 8 +
                                          (lane & 7)) * TSTRIDE)
                              + kb + ((lane >> 3) & 1) * 16;
                ldsm4(bh[p], base + A2TILE + rb);
            }
#pragma unroll
            for (int im = 0; im < 2; ++im)
#pragma unroll
                for (int j = 0; j < 10; ++j)
                    mma16816h(acc[im][j], a[im], &bh[j >> 1][(j & 1) * 2]);
        }
        if (c + 2 < NC) {
            int ns = stage + 2;
            if (ns >= 3) ns -= 3;
            load_stage(c + 2, ns);
        }
        if (++stage == 3) stage = 0;
    }
    cpa_wait<0>();
    __syncthreads();

    // epilogue: stage 64-row chunks in smem (row stride 164 floats), coalesced out
    float* ep = reinterpret_cast<float*>(smem);
    float* out = Cp + (size_t)blockIdx.z * (N_NODES * F2);
#pragma unroll
    for (int chunk = 0; chunk < 2; ++chunk) {
        if ((wm >> 1) == chunk) {
            int rbase = (wm & 1) * 32;
#pragma unroll
            for (int im = 0; im < 2; ++im)
#pragma unroll
                for (int j = 0; j < 10; ++j) {
                    int r = rbase + im * 16 + (lane >> 2);
                    int cc = wn * 80 + j * 8 + (lane & 3) * 2;
                    *(float2*)&ep[r * 164 + cc] =
                        make_float2(acc[im][j][0], acc[im][j][1]);
                    *(float2*)&ep[(r + 8) * 164 + cc] =
                        make_float2(acc[im][j][2], acc[im][j][3]);
                }
        }
        __syncthreads();
#pragma unroll
        for (int it = 0; it < 10; ++it) {
            int idx = tid + it * 256;        // 0..2559
            int row = idx / 40, c4 = idx % 40;
            float4 v = *reinterpret_cast<float4*>(&ep[row * 164 + c4 * 4]);
            *reinterpret_cast<float4*>(
                &out[(size_t)(m0 + chunk * 64 + row) * F2 + c4 * 4]) = v;
        }
        __syncthreads();
    }
}

// ------------- split-K reduce (deterministic) + fused alpha2 dots ------------
__global__ __launch_bounds__(160)
void k_reduce_alpha2(const float* __restrict__ att_s, const float* __restrict__ att_d) {
    const int n = blockIdx.x;
    const int t = threadIdx.x;          // 0..159
    const int lane = t & 31, head = t >> 5;
    float s = 0.f;
#pragma unroll
    for (int z = 0; z < KSPLIT; ++z)
        s += g_h2p[(size_t)z * (N_NODES * F2) + n * F2 + t];
    g_h2[n * F2 + t] = s;
    float vs = s * att_s[t];
    float vd = s * att_d[t];
#pragma unroll
    for (int o = 16; o > 0; o >>= 1) {
        vs += __shfl_down_sync(0xffffffffu, vs, o);
        vd += __shfl_down_sync(0xffffffffu, vd, o);
    }
    if (!lane) { g_as2[n * H2 + head] = vs; g_ad2[n * H2 + head] = vd; }
}

// ------------------------------ layer-1 aggregation + ELU + fp16 out ---------
__global__ __launch_bounds__(256)
void k_agg1(const float* __restrict__ b1) {
    const int n = blockIdx.x;
    const int t = threadIdx.x;
    const int start = g_off[n];
    const int deg = g_off[n + 1] - start;

    __shared__ float sh_m[H1], sh_den[H1], sh_ad[H1];
    __shared__ float sh_w[32 * H1];
    __shared__ int   s_src[32];
    __shared__ float pm[4][H1], pd[4][H1];

    // softmax max/denominator: 4-way parallel over edges, online per stripe
    {
        const int h = t & 63, quarter = t >> 6;
        float adv = g_ad1[n * H1 + h];
        float m = -1e30f, den = 0.f;
        for (int e = quarter; e < deg; e += 4) {
            int s = g_csr_src[start + e];
            float l = g_as1[s * H1 + h] + adv;
            l = l > 0.f ? l : 0.2f * l;
            if (l > m) { den = den * __expf(m - l) + 1.f; m = l; }
            else       { den += __expf(l - m); }
        }
        pm[quarter][h] = m;
        pd[quarter][h] = den;
        if (quarter == 0) sh_ad[h] = adv;
    }
    __syncthreads();
    if (t < H1) {
        float m0 = pm[0][t], m1 = pm[1][t], m2 = pm[2][t], m3 = pm[3][t];
        float M = fmaxf(fmaxf(m0, m1), fmaxf(m2, m3));
        float D = pd[0][t] * __expf(m0 - M) + pd[1][t] * __expf(m1 - M) +
                  pd[2][t] * __expf(m2 - M) + pd[3][t] * __expf(m3 - M);
        sh_m[t] = M; sh_den[t] = D;
    }
    __syncthreads();

    float acc[16];
#pragma unroll
    for (int i = 0; i < 16; i++) acc[i] = 0.f;
    const int h = t >> 2;  // head of this thread's 16-feature slice

    for (int e0 = 0; e0 < deg; e0 += 32) {
        int ce = min(32, deg - e0);
        if (t < ce) s_src[t] = g_csr_src[start + e0 + t];
        __syncthreads();
        for (int k = t; k < ce * H1; k += 256) {
            int e = k >> 6, hh = k & 63;
            float l = g_as1[s_src[e] * H1 + hh] + sh_ad[hh];
            l = l > 0.f ? l : 0.2f * l;
            sh_w[k] = __expf(l - sh_m[hh]);
        }
        __syncthreads();
#pragma unroll 2
        for (int e = 0; e < ce; e++) {
            const uint4* hp = reinterpret_cast<const uint4*>(
                g_h1 + (size_t)s_src[e] * F1 + t * 16);
            float wv = sh_w[(e << 6) + h];
#pragma unroll
            for (int q = 0; q < 2; q++) {
                uint4 u = hp[q];
                float2 f0 = __half22float2(*(const __half2*)&u.x);
                float2 f1 = __half22float2(*(const __half2*)&u.y);
                float2 f2 = __half22float2(*(const __half2*)&u.z);
                float2 f3 = __half22float2(*(const __half2*)&u.w);
                acc[8 * q + 0] += wv * f0.x;
                acc[8 * q + 1] += wv * f0.y;
                acc[8 * q + 2] += wv * f1.x;
                acc[8 * q + 3] += wv * f1.y;
                acc[8 * q + 4] += wv * f2.x;
                acc[8 * q + 5] += wv * f2.y;
                acc[8 * q + 6] += wv * f3.x;
                acc[8 * q + 7] += wv * f3.y;
            }
        }
        __syncthreads();
    }

    float invden = 1.f / sh_den[h];
    const float4* bp = reinterpret_cast<const float4*>(b1 + t * 16);
    float vals[16];
#pragma unroll
    for (int q = 0; q < 4; q++) {
        float4 bv = bp[q];
        float v0 = acc[4 * q + 0] * invden + bv.x;
        float v1 = acc[4 * q + 1] * invden + bv.y;
        float v2 = acc[4 * q + 2] * invden + bv.z;
        float v3 = acc[4 * q + 3] * invden + bv.w;
        vals[4 * q + 0] = v0 > 0.f ? v0 : __expf(v0) - 1.f;
        vals[4 * q + 1] = v1 > 0.f ? v1 : __expf(v1) - 1.f;
        vals[4 * q + 2] = v2 > 0.f ? v2 : __expf(v2) - 1.f;
        vals[4 * q + 3] = v3 > 0.f ? v3 : __expf(v3) - 1.f;
    }
    uint32_t pk[8];
#pragma unroll
    for (int i = 0; i < 8; i++) {
        __half2 hv = __floats2half2_rn(vals[2 * i], vals[2 * i + 1]);
        pk[i] = *reinterpret_cast<uint32_t*>(&hv);
    }
    size_t off = (size_t)n * F1 + t * 16;
    uint4* op = reinterpret_cast<uint4*>(g_x1 + off);
    op[0] = make_uint4(pk[0], pk[1], pk[2], pk[3]);
    op[1] = make_uint4(pk[4], pk[5], pk[6], pk[7]);
}

// ------------------------------ layer-2 aggregation + head mean --------------
__global__ __launch_bounds__(192)
void k_agg2(const float* __restrict__ b2) {
    const int n = blockIdx.x;
    const int t = threadIdx.x;
    const int start = g_off[n];
    const int deg = g_off[n + 1] - start;

    __shared__ float sh_m[H2], sh_den[H2], sh_ad[H2];
    __shared__ float sh_r[F2];
    __shared__ float pm2[4][H2], pd2[4][H2];

    // phase 1: 4-way striped online softmax over edges (20 threads)
    if (t < 20) {
        const int stripe = t / 5, hh = t % 5;
        float adv = g_ad2[n * H2 + hh];
        float m = -1e30f, den = 0.f;
        for (int e = stripe; e < deg; e += 4) {
            int s = g_csr_src[start + e];
            float l = g_as2[s * H2 + hh] + adv;
            l = l > 0.f ? l : 0.2f * l;
            if (l > m) { den = den * __expf(m - l) + 1.f; m = l; }
            else       { den += __expf(l - m); }
        }
        pm2[stripe][hh] = m;
        pd2[stripe][hh] = den;
        if (stripe == 0) sh_ad[hh] = adv;
    }
    __syncthreads();
    if (t < H2) {
        float m0 = pm2[0][t], m1 = pm2[1][t], m2 = pm2[2][t], m3 = pm2[3][t];
        float M = fmaxf(fmaxf(m0, m1), fmaxf(m2, m3));
        float D = pd2[0][t] * __expf(m0 - M) + pd2[1][t] * __expf(m1 - M) +
                  pd2[2][t] * __expf(m2 - M) + pd2[3][t] * __expf(m3 - M);
        sh_m[t] = M; sh_den[t] = D;
    }
    __syncthreads();

    if (t < F2) {
        int hh = t >> 5;
        float m = sh_m[hh], adv = sh_ad[hh];
        float acc = 0.f;
        for (int e = 0; e < deg; e++) {
            int s = g_csr_src[start + e];
            float l = g_as2[s * H2 + hh] + adv;
            l = l > 0.f ? l : 0.2f * l;
            acc += __expf(l - m) * g_h2[s * F2 + t];
        }
        sh_r[t] = acc / sh_den[hh];
    }
    __syncthreads();

    if (t < OUTF) {
        float v = (sh_r[t] + sh_r[32 + t] + sh_r[64 + t] + sh_r[96 + t] +
                   sh_r[128 + t]) * 0.2f + b2[t];
        g_x2[n * OUTF + t] = v;
    }
}

// ------------------------------ bond scores + softmax ------------------------
__global__ void k_score(const int* __restrict__ lefts,
                        const int* __restrict__ rights,
                        float* __restrict__ out) {
    __shared__ float sm[NB];
    int t = threadIdx.x;
    int l = lefts[t], r = rights[t];
    float s = 0.f;
#pragma unroll
    for (int c = 0; c < OUTF; c++) s += g_x2[l * OUTF + c] + g_x2[r * OUTF + c];
    sm[t] = s;
    __syncthreads();
    float mx = -1e30f;
    for (int j = 0; j < NB; j++) mx = fmaxf(mx, sm[j]);
    float e = __expf(s - mx);
    __syncthreads();
    sm[t] = e;
    __syncthreads();
    float sum = 0.f;
    for (int j = 0; j < NB; j++) sum += sm[j];
    out[t] = e / sum;
}

// ------------------------------ launch ---------------------------------------
extern "C" void kernel_launch(void* const* d_in, const int* in_sizes, int n_in,
                              void* d_out, int out_size) {
    const float* x   = (const float*)d_in[0];
    const int*   ei  = (const int*)d_in[1];
    const int*   lf  = (const int*)d_in[2];
    const int*   rt  = (const int*)d_in[3];
    const float* W1  = (const float*)d_in[4];
    const float* as1 = (const float*)d_in[5];
    const float* ad1 = (const float*)d_in[6];
    const float* b1  = (const float*)d_in[7];
    const float* W2  = (const float*)d_in[8];
    const float* as2 = (const float*)d_in[9];
    const float* ad2 = (const float*)d_in[10];
    const float* b2  = (const float*)d_in[11];
    float* out = (float*)d_out;

    cudaFuncSetAttribute(gemm1_mma, cudaFuncAttributeMaxDynamicSharedMemorySize,
                         GEMM1_SMEM);
    cudaFuncSetAttribute(gemm2_mma, cudaFuncAttributeMaxDynamicSharedMemorySize,
                         GEMM2_SMEM);

    void *p_xf, *p_w1h, *p_w2h;
    void *p_h1, *p_h2p, *p_x1;
    cudaGetSymbolAddress(&p_xf, g_xf);
    cudaGetSymbolAddress(&p_w1h, g_w1h);
    cudaGetSymbolAddress(&p_w2h, g_w2h);
    cudaGetSymbolAddress(&p_h1, g_h1);
    cudaGetSymbolAddress(&p_h2p, g_h2p);
    cudaGetSymbolAddress(&p_x1, g_x1);

    // fused input conversions + edge counting
    k_prep<<<(NSPLIT + 255) / 256, 256>>>(x, W1, W2, ei);

    // CSR by destination (scan adds self-loops, resets counts)
    k_scan<<<1, 1024>>>();
    k_scatter<<<(ETOT + 255) / 256, 256>>>(ei);

    // layer 1: h1 = x @ W1^T (fp16 out) + fused alpha1
    gemm1_mma<<<dim3(F1 / 128, N_NODES / 128), 256, GEMM1_SMEM>>>(
        (const __half*)p_xf, (const __half*)p_w1h, (__half*)p_h1, as1, ad1);
    k_agg1<<<N_NODES, 256>>>(b1);

    // layer 2: h2 = x1 @ W2^T, split-K x4 + fused reduce/alpha2
    gemm2_mma<<<dim3(1, N_NODES / 128, KSPLIT), 256, GEMM2_SMEM>>>(
        (const __half*)p_x1, (const __half*)p_w2h, (float*)p_h2p);
    k_reduce_alpha2<<<N_NODES, 160>>>(as2, ad2);
    k_agg2<<<N_NODES, 192>>>(b2);

    // bonds
    k_score<<<1, NB>>>(lf, rt, out);
}

// round 14
// speedup vs baseline: 1.0363x; 1.0363x over previous
#include <cuda_runtime.h>
#include <cuda_bf16.h>
#include <cuda_fp16.h>
#include <stdint.h>
#include <math.h>

#define N_NODES 8192
#define NE      49152
#define ETOT    (NE + N_NODES)       // 57344
#define IN_F    128
#define H1      64
#define HID     64
#define F1      (H1*HID)             // 4096
#define H2      5
#define OUTF    32
#define F2      (H2*OUTF)            // 160
#define NB      64
#define KSPLIT  4
#define KSLC    (F1 / KSPLIT)        // 1024

// ------------------------------ scratch (static, no allocation) --------------
__device__ __half g_h1[(size_t)N_NODES * F1];                // 67 MB
__device__ __half g_x1[(size_t)N_NODES * F1];                // 67 MB
__device__ __half g_xf[N_NODES * IN_F];
__device__ __half g_w1h[F1 * IN_F];
__device__ __half g_w2h[F2 * F1];
__device__ float g_as1[N_NODES * H1];
__device__ float g_ad1[N_NODES * H1];
__device__ float g_h2p[(size_t)KSPLIT * N_NODES * F2];
__device__ float g_h2[N_NODES * F2];
__device__ float g_as2[N_NODES * H2];
__device__ float g_ad2[N_NODES * H2];
__device__ float g_x2[N_NODES * OUTF];
__device__ int   g_counts[N_NODES];   // zero at start of every call (scan resets)
__device__ int   g_off[N_NODES + 1];
__device__ int   g_cursor[N_NODES];
__device__ int   g_csr_src[ETOT];

// ------------------------------ PTX helpers ----------------------------------
__device__ __forceinline__ uint32_t smem_u32(const void* p) {
    uint32_t a;
    asm("{ .reg .u64 t; cvta.to.shared.u64 t, %1; cvt.u32.u64 %0, t; }"
        : "=r"(a) : "l"(p));
    return a;
}

__device__ __forceinline__ void cpa16(uint32_t d, const void* s) {
    asm volatile("cp.async.cg.shared.global [%0], [%1], 16;" :: "r"(d), "l"(s));
}
__device__ __forceinline__ void cpa_commit() {
    asm volatile("cp.async.commit_group;" ::: "memory");
}
template <int N> __device__ __forceinline__ void cpa_wait() {
    asm volatile("cp.async.wait_group %0;" :: "n"(N) : "memory");
}

__device__ __forceinline__ void ldsm4(uint32_t* r, uint32_t addr) {
    asm volatile("ldmatrix.sync.aligned.m8n8.x4.shared.b16 {%0,%1,%2,%3}, [%4];"
                 : "=r"(r[0]), "=r"(r[1]), "=r"(r[2]), "=r"(r[3]) : "r"(addr));
}

__device__ __forceinline__ void mma16816h(float* c, const uint32_t* a,
                                          const uint32_t* b) {
    asm volatile(
        "mma.sync.aligned.m16n8k16.row.col.f32.f16.f16.f32 "
        "{%0,%1,%2,%3}, {%4,%5,%6,%7}, {%8,%9}, {%0,%1,%2,%3};"
        : "+f"(c[0]), "+f"(c[1]), "+f"(c[2]), "+f"(c[3])
        : "r"(a[0]), "r"(a[1]), "r"(a[2]), "r"(a[3]), "r"(b[0]), "r"(b[1]));
}

// --------- fused input conversion (x4 vectorized) + edge counting ------------
#define NXE (N_NODES * IN_F)     // 1048576
#define NW1 (F1 * IN_F)          // 524288
#define NW2 (F2 * F1)            // 655360
#define NSPLIT (NXE + NW1 + NW2)
#define NPREP (NSPLIT / 4)       // 557056

__global__ void k_prep(const float* __restrict__ x, const float* __restrict__ W1,
                       const float* __restrict__ W2, const int* __restrict__ ei) {
    int i = blockIdx.x * blockDim.x + threadIdx.x;
    if (i < NE) atomicAdd(&g_counts[ei[NE + i]], 1);   // edge degree count
    if (i >= NPREP) return;
    int base = i * 4;
    const float* src;
    __half* dst;
    int k;
    if (base < NXE)            { src = x;  dst = g_xf;  k = base; }
    else if (base < NXE + NW1) { src = W1; dst = g_w1h; k = base - NXE; }
    else                       { src = W2; dst = g_w2h; k = base - NXE - NW1; }
    float4 v = *reinterpret_cast<const float4*>(src + k);
    __half2 h0 = __floats2half2_rn(v.x, v.y);
    __half2 h1 = __floats2half2_rn(v.z, v.w);
    uint32_t* o = reinterpret_cast<uint32_t*>(dst + k);
    o[0] = *reinterpret_cast<uint32_t*>(&h0);
    o[1] = *reinterpret_cast<uint32_t*>(&h1);
}

// ------------------------------ CSR scan (adds self-loop, resets counts) -----
__global__ void k_scan() {
    __shared__ int sh[1024];
    int t = threadIdx.x;
    int loc[8];
    int s = 0;
#pragma unroll
    for (int j = 0; j < 8; j++) {
        int idx = t * 8 + j;
        loc[j] = g_counts[idx] + 1;    // +1 self-loop
        g_counts[idx] = 0;             // reset for next call (graph replay)
        s += loc[j];
    }
    sh[t] = s;
    __syncthreads();
    for (int off = 1; off < 1024; off <<= 1) {
        int v = (t >= off) ? sh[t - off] : 0;
        __syncthreads();
        sh[t] += v;
        __syncthreads();
    }
    int run = (t == 0) ? 0 : sh[t - 1];
#pragma unroll
    for (int j = 0; j < 8; j++) {
        int idx = t * 8 + j;
        g_off[idx] = run;
        g_cursor[idx] = run;
        run += loc[j];
    }
    if (t == 1023) g_off[N_NODES] = run;
}

__global__ void k_scatter(const int* __restrict__ ei) {
    int i = blockIdx.x * blockDim.x + threadIdx.x;
    if (i >= ETOT) return;
    int src, dst;
    if (i < NE) { src = ei[i]; dst = ei[NE + i]; }
    else        { src = i - NE; dst = src; }
    int pos = atomicAdd(&g_cursor[dst], 1);
    g_csr_src[pos] = src;
}

// ------------------------------ GEMM1 (whole-K resident + fused alpha) -------
#define T1S     272                       // bytes per smem row (17 x 16B)
#define T1TILE  (128 * T1S)               // 34816 B
#define GEMM1_SMEM (2 * T1TILE)           // 69632 B

__global__ __launch_bounds__(256, 2)
void gemm1_mma(const __half* __restrict__ Af, const __half* __restrict__ Bh,
               __half* __restrict__ C,
               const float* __restrict__ att_s, const float* __restrict__ att_d) {
    extern __shared__ char smem[];
    const int N = F1, K = IN_F;
    const int tid = threadIdx.x;
    const int wid = tid >> 5, lane = tid & 31;
    const int m0 = blockIdx.y * 128, n0 = blockIdx.x * 128;
    const int wm = wid >> 1, wn = wid & 1;
    const uint32_t sb = smem_u32(smem);

#pragma unroll
    for (int i = tid; i < 2048; i += 256) {
        int r = i >> 4, seg = i & 15;
        uint32_t off = (uint32_t)(r * T1S + seg * 16);
        cpa16(sb + off, Af + (size_t)(m0 + r) * K + seg * 8);
        cpa16(sb + T1TILE + off, Bh + (size_t)(n0 + r) * K + seg * 8);
    }
    cpa_commit();

    float acc[2][8][4];
#pragma unroll
    for (int im = 0; im < 2; ++im)
#pragma unroll
        for (int j = 0; j < 8; ++j)
#pragma unroll
            for (int q = 0; q < 4; ++q) acc[im][j][q] = 0.f;

    cpa_wait<0>();
    __syncthreads();

#pragma unroll
    for (int ks = 0; ks < 8; ++ks) {
        const uint32_t kb = ks * 32;
        uint32_t a[2][4], bh[4][4];
#pragma unroll
        for (int im = 0; im < 2; ++im) {
            uint32_t ra = (uint32_t)((wm * 32 + im * 16 + (lane & 15)) * T1S)
                          + kb + ((lane >> 4) & 1) * 16;
            ldsm4(a[im], sb + ra);
        }
#pragma unroll
        for (int p = 0; p < 4; ++p) {
            uint32_t rb = (uint32_t)((wn * 64 + p * 16 + ((lane >> 4) & 1) * 8 +
                                      (lane & 7)) * T1S)
                          + kb + ((lane >> 3) & 1) * 16;
            ldsm4(bh[p], sb + T1TILE + rb);
        }
#pragma unroll
        for (int im = 0; im < 2; ++im)
#pragma unroll
            for (int j = 0; j < 8; ++j)
                mma16816h(acc[im][j], a[im], &bh[j >> 1][(j & 1) * 2]);
    }
    __syncthreads();   // tiles dead; smem becomes epilogue staging

    // epilogue 1a: stage fp16 tile into smem (row stride 68 u32 = 272 B)
    uint32_t* ep = reinterpret_cast<uint32_t*>(smem);
#pragma unroll
    for (int im = 0; im < 2; ++im)
#pragma unroll
        for (int j = 0; j < 8; ++j) {
            int r = wm * 32 + im * 16 + (lane >> 2);
            int c32 = wn * 32 + j * 4 + (lane & 3);
            __half2 v0 = __floats2half2_rn(acc[im][j][0], acc[im][j][1]);
            __half2 v1 = __floats2half2_rn(acc[im][j][2], acc[im][j][3]);
            ep[r * 68 + c32] = *reinterpret_cast<uint32_t*>(&v0);
            ep[(r + 8) * 68 + c32] = *reinterpret_cast<uint32_t*>(&v1);
        }

    // epilogue 2: fused attention dots (register-only)
    const int head = (blockIdx.x << 1) + wn;
    float as_att[16], ad_att[16];
#pragma unroll
    for (int j = 0; j < 8; ++j) {
        int cc = head * HID + j * 8 + (lane & 3) * 2;
        as_att[2 * j] = att_s[cc];     as_att[2 * j + 1] = att_s[cc + 1];
        ad_att[2 * j] = att_d[cc];     ad_att[2 * j + 1] = att_d[cc + 1];
    }
#pragma unroll
    for (int im = 0; im < 2; ++im) {
        float s0 = 0.f, s1 = 0.f, d0 = 0.f, d1 = 0.f;
#pragma unroll
        for (int j = 0; j < 8; ++j) {
            s0 += acc[im][j][0] * as_att[2 * j] + acc[im][j][1] * as_att[2 * j + 1];
            s1 += acc[im][j][2] * as_att[2 * j] + acc[im][j][3] * as_att[2 * j + 1];
            d0 += acc[im][j][0] * ad_att[2 * j] + acc[im][j][1] * ad_att[2 * j + 1];
            d1 += acc[im][j][2] * ad_att[2 * j] + acc[im][j][3] * ad_att[2 * j + 1];
        }
#pragma unroll
        for (int o = 1; o < 4; o <<= 1) {
            s0 += __shfl_xor_sync(0xffffffffu, s0, o);
            s1 += __shfl_xor_sync(0xffffffffu, s1, o);
            d0 += __shfl_xor_sync(0xffffffffu, d0, o);
            d1 += __shfl_xor_sync(0xffffffffu, d1, o);
        }
        if ((lane & 3) == 0) {
            int r = m0 + wm * 32 + im * 16 + (lane >> 2);
            g_as1[r * H1 + head] = s0;
            g_ad1[r * H1 + head] = d0;
            g_as1[(r + 8) * H1 + head] = s1;
            g_ad1[(r + 8) * H1 + head] = d1;
        }
    }

    // epilogue 1b: coalesced 16B stores
    __syncthreads();
#pragma unroll
    for (int it = 0; it < 8; ++it) {
        int idx = tid + it * 256;
        int row = idx >> 4, c16 = idx & 15;
        uint4 v = *reinterpret_cast<uint4*>(&ep[row * 68 + c16 * 4]);
        *reinterpret_cast<uint4*>(&C[(size_t)(m0 + row) * N + n0 + c16 * 8]) = v;
    }
}

// ------------------------------ GEMM2 (split-K x4, BN=160, 2-stage) ----------
#define TSTRIDE 80
#define A2TILE (128 * TSTRIDE)            // 10240
#define B2TILE (160 * TSTRIDE)            // 12800
#define STAGE2 (A2TILE + B2TILE)          // 23040
#define GEMM2_SMEM (2 * STAGE2)           // 46080 (also >= 64*164*4 staging)

__global__ __launch_bounds__(256, 2)
void gemm2_mma(const __half* __restrict__ Af, const __half* __restrict__ Bh,
               float* __restrict__ Cp) {
    extern __shared__ char smem[];
    const int K = F1;
    const int tid = threadIdx.x;
    const int wid = tid >> 5, lane = tid & 31;
    const int m0 = blockIdx.y * 128;
    const size_t kb0 = (size_t)blockIdx.z * KSLC;
    const int wm = wid >> 1, wn = wid & 1;
    const int NC = KSLC >> 5;             // 32
    const uint32_t sb = smem_u32(smem);

    float acc[2][10][4];
#pragma unroll
    for (int im = 0; im < 2; ++im)
#pragma unroll
        for (int j = 0; j < 10; ++j)
#pragma unroll
            for (int q = 0; q < 4; ++q) acc[im][j][q] = 0.f;

    auto load_stage = [&](int c, int s) {
        uint32_t base = sb + (uint32_t)s * STAGE2;
        const size_t kc = kb0 + (size_t)c * 32;
#pragma unroll
        for (int i = tid; i < 512; i += 256) {
            int r = i >> 2, seg = i & 3;
            uint32_t off = (uint32_t)(r * TSTRIDE + seg * 16);
            cpa16(base + off, Af + (size_t)(m0 + r) * K + kc + seg * 8);
        }
#pragma unroll
        for (int i = tid; i < 640; i += 256) {
            int r = i >> 2, seg = i & 3;
            uint32_t off = (uint32_t)(r * TSTRIDE + seg * 16);
            cpa16(base + A2TILE + off, Bh + (size_t)r * K + kc + seg * 8);
        }
        cpa_commit();
    };

    load_stage(0, 0);
    for (int c = 0; c < NC; ++c) {
        if (c + 1 < NC) {
            load_stage(c + 1, (c + 1) & 1);
            cpa_wait<1>();
        } else {
            cpa_wait<0>();
        }
        __syncthreads();

        const uint32_t base = sb + (uint32_t)(c & 1) * STAGE2;
#pragma unroll
        for (int ks = 0; ks < 2; ++ks) {
            const uint32_t kb = ks * 32;
            uint32_t a[2][4], bh[5][4];
#pragma unroll
            for (int im = 0; im < 2; ++im) {
                uint32_t ra = (uint32_t)((wm * 32 + im * 16 + (lane & 15)) * TSTRIDE)
                              + kb + ((lane >> 4) & 1) * 16;
                ldsm4(a[im], base + ra);
            }
#pragma unroll
            for (int p = 0; p < 5; ++p) {
                uint32_t rb = (uint32_t)((wn * 80 + p * 16 + ((lane >> 4) & 1) * 8 +
                                          (lane & 7)) * TSTRIDE)
                              + kb + ((lane >> 3) & 1) * 16;
                ldsm4(bh[p], base + A2TILE + rb);
            }
#pragma unroll
            for (int im = 0; im < 2; ++im)
#pragma unroll
                for (int j = 0; j < 10; ++j)
                    mma16816h(acc[im][j], a[im], &bh[j >> 1][(j & 1) * 2]);
        }
        __syncthreads();
    }

    // epilogue: stage 64-row chunks in smem (row stride 164 floats), coalesced out
    float* ep = reinterpret_cast<float*>(smem);
    float* out = Cp + (size_t)blockIdx.z * (N_NODES * F2);
#pragma unroll
    for (int chunk = 0; chunk < 2; ++chunk) {
        if ((wm >> 1) == chunk) {
            int rbase = (wm & 1) * 32;
#pragma unroll
            for (int im = 0; im < 2; ++im)
#pragma unroll
                for (int j = 0; j < 10; ++j) {
                    int r = rbase + im * 16 + (lane >> 2);
                    int cc = wn * 80 + j * 8 + (lane & 3) * 2;
                    *(float2*)&ep[r * 164 + cc] =
                        make_float2(acc[im][j][0], acc[im][j][1]);
                    *(float2*)&ep[(r + 8) * 164 + cc] =
                        make_float2(acc[im][j][2], acc[im][j][3]);
                }
        }
        __syncthreads();
#pragma unroll
        for (int it = 0; it < 10; ++it) {
            int idx = tid + it * 256;
            int row = idx / 40, c4 = idx % 40;
            float4 v = *reinterpret_cast<float4*>(&ep[row * 164 + c4 * 4]);
            *reinterpret_cast<float4*>(
                &out[(size_t)(m0 + chunk * 64 + row) * F2 + c4 * 4]) = v;
        }
        __syncthreads();
    }
}

// ------------- split-K reduce (deterministic) + fused alpha2 dots ------------
__global__ __launch_bounds__(160)
void k_reduce_alpha2(const float* __restrict__ att_s, const float* __restrict__ att_d) {
    const int n = blockIdx.x;
    const int t = threadIdx.x;
    const int lane = t & 31, head = t >> 5;
    float s = 0.f;
#pragma unroll
    for (int z = 0; z < KSPLIT; ++z)
        s += g_h2p[(size_t)z * (N_NODES * F2) + n * F2 + t];
    g_h2[n * F2 + t] = s;
    float vs = s * att_s[t];
    float vd = s * att_d[t];
#pragma unroll
    for (int o = 16; o > 0; o >>= 1) {
        vs += __shfl_down_sync(0xffffffffu, vs, o);
        vd += __shfl_down_sync(0xffffffffu, vd, o);
    }
    if (!lane) { g_as2[n * H2 + head] = vs; g_ad2[n * H2 + head] = vd; }
}

// ------------------------------ layer-1 aggregation + ELU + fp16 out ---------
__global__ __launch_bounds__(256)
void k_agg1(const float* __restrict__ b1) {
    const int n = blockIdx.x;
    const int t = threadIdx.x;
    const int start = g_off[n];
    const int deg = g_off[n + 1] - start;

    __shared__ float sh_m[H1], sh_den[H1], sh_ad[H1];
    __shared__ float sh_w[32 * H1];
    __shared__ int   s_src[32];
    __shared__ float pm[4][H1], pd[4][H1];

    // softmax max/denominator: 4-way parallel over edges, online per stripe
    {
        const int h = t & 63, quarter = t >> 6;
        float adv = g_ad1[n * H1 + h];
        float m = -1e30f, den = 0.f;
        for (int e = quarter; e < deg; e += 4) {
            int s = g_csr_src[start + e];
            float l = g_as1[s * H1 + h] + adv;
            l = l > 0.f ? l : 0.2f * l;
            if (l > m) { den = den * __expf(m - l) + 1.f; m = l; }
            else       { den += __expf(l - m); }
        }
        pm[quarter][h] = m;
        pd[quarter][h] = den;
        if (quarter == 0) sh_ad[h] = adv;
    }
    __syncthreads();
    if (t < H1) {
        float m0 = pm[0][t], m1 = pm[1][t], m2 = pm[2][t], m3 = pm[3][t];
        float M = fmaxf(fmaxf(m0, m1), fmaxf(m2, m3));
        float D = pd[0][t] * __expf(m0 - M) + pd[1][t] * __expf(m1 - M) +
                  pd[2][t] * __expf(m2 - M) + pd[3][t] * __expf(m3 - M);
        sh_m[t] = M; sh_den[t] = D;
    }
    __syncthreads();

    float acc[16];
#pragma unroll
    for (int i = 0; i < 16; i++) acc[i] = 0.f;
    const int h = t >> 2;

    for (int e0 = 0; e0 < deg; e0 += 32) {
        int ce = min(32, deg - e0);
        if (t < ce) s_src[t] = g_csr_src[start + e0 + t];
        __syncthreads();
        for (int k = t; k < ce * H1; k += 256) {
            int e = k >> 6, hh = k & 63;
            float l = g_as1[s_src[e] * H1 + hh] + sh_ad[hh];
            l = l > 0.f ? l : 0.2f * l;
            sh_w[k] = __expf(l - sh_m[hh]);
        }
        __syncthreads();
        for (int e = 0; e < ce; e++) {
            const uint4* hp = reinterpret_cast<const uint4*>(
                g_h1 + (size_t)s_src[e] * F1 + t * 16);
            float wv = sh_w[(e << 6) + h];
#pragma unroll
            for (int q = 0; q < 2; q++) {
                uint4 u = hp[q];
                float2 f0 = __half22float2(*(const __half2*)&u.x);
                float2 f1 = __half22float2(*(const __half2*)&u.y);
                float2 f2 = __half22float2(*(const __half2*)&u.z);
                float2 f3 = __half22float2(*(const __half2*)&u.w);
                acc[8 * q + 0] += wv * f0.x;
                acc[8 * q + 1] += wv * f0.y;
                acc[8 * q + 2] += wv * f1.x;
                acc[8 * q + 3] += wv * f1.y;
                acc[8 * q + 4] += wv * f2.x;
                acc[8 * q + 5] += wv * f2.y;
                acc[8 * q + 6] += wv * f3.x;
                acc[8 * q + 7] += wv * f3.y;
            }
        }
        __syncthreads();
    }

    float invden = 1.f / sh_den[h];
    const float4* bp = reinterpret_cast<const float4*>(b1 + t * 16);
    float vals[16];
#pragma unroll
    for (int q = 0; q < 4; q++) {
        float4 bv = bp[q];
        float v0 = acc[4 * q + 0] * invden + bv.x;
        float v1 = acc[4 * q + 1] * invden + bv.y;
        float v2 = acc[4 * q + 2] * invden + bv.z;
        float v3 = acc[4 * q + 3] * invden + bv.w;
        vals[4 * q + 0] = v0 > 0.f ? v0 : __expf(v0) - 1.f;
        vals[4 * q + 1] = v1 > 0.f ? v1 : __expf(v1) - 1.f;
        vals[4 * q + 2] = v2 > 0.f ? v2 : __expf(v2) - 1.f;
        vals[4 * q + 3] = v3 > 0.f ? v3 : __expf(v3) - 1.f;
    }
    uint32_t pk[8];
#pragma unroll
    for (int i = 0; i < 8; i++) {
        __half2 hv = __floats2half2_rn(vals[2 * i], vals[2 * i + 1]);
        pk[i] = *reinterpret_cast<uint32_t*>(&hv);
    }
    size_t off = (size_t)n * F1 + t * 16;
    uint4* op = reinterpret_cast<uint4*>(g_x1 + off);
    op[0] = make_uint4(pk[0], pk[1], pk[2], pk[3]);
    op[1] = make_uint4(pk[4], pk[5], pk[6], pk[7]);
}

// ------------------------------ layer-2 aggregation + head mean --------------
__global__ __launch_bounds__(192)
void k_agg2(const float* __restrict__ b2) {
    const int n = blockIdx.x;
    const int t = threadIdx.x;
    const int start = g_off[n];
    const int deg = g_off[n + 1] - start;

    __shared__ float sh_m[H2], sh_den[H2], sh_ad[H2];
    __shared__ float sh_r[F2];
    __shared__ float pm2[4][H2], pd2[4][H2];

    if (t < 20) {
        const int stripe = t / 5, hh = t % 5;
        float adv = g_ad2[n * H2 + hh];
        float m = -1e30f, den = 0.f;
        for (int e = stripe; e < deg; e += 4) {
            int s = g_csr_src[start + e];
            float l = g_as2[s * H2 + hh] + adv;
            l = l > 0.f ? l : 0.2f * l;
            if (l > m) { den = den * __expf(m - l) + 1.f; m = l; }
            else       { den += __expf(l - m); }
        }
        pm2[stripe][hh] = m;
        pd2[stripe][hh] = den;
        if (stripe == 0) sh_ad[hh] = adv;
    }
    __syncthreads();
    if (t < H2) {
        float m0 = pm2[0][t], m1 = pm2[1][t], m2 = pm2[2][t], m3 = pm2[3][t];
        float M = fmaxf(fmaxf(m0, m1), fmaxf(m2, m3));
        float D = pd2[0][t] * __expf(m0 - M) + pd2[1][t] * __expf(m1 - M) +
                  pd2[2][t] * __expf(m2 - M) + pd2[3][t] * __expf(m3 - M);
        sh_m[t] = M; sh_den[t] = D;
    }
    __syncthreads();

    if (t < F2) {
        int hh = t >> 5;
        float m = sh_m[hh], adv = sh_ad[hh];
        float acc = 0.f;
        for (int e = 0; e < deg; e++) {
            int s = g_csr_src[start + e];
            float l = g_as2[s * H2 + hh] + adv;
            l = l > 0.f ? l : 0.2f * l;
            acc += __expf(l - m) * g_h2[s * F2 + t];
        }
        sh_r[t] = acc / sh_den[hh];
    }
    __syncthreads();

    if (t < OUTF) {
        float v = (sh_r[t] + sh_r[32 + t] + sh_r[64 + t] + sh_r[96 + t] +
                   sh_r[128 + t]) * 0.2f + b2[t];
        g_x2[n * OUTF + t] = v;
    }
}

// ------------------------------ bond scores + softmax ------------------------
__global__ void k_score(const int* __restrict__ lefts,
                        const int* __restrict__ rights,
                        float* __restrict__ out) {
    __shared__ float sm[NB];
    int t = threadIdx.x;
    int l = lefts[t], r = rights[t];
    float s = 0.f;
#pragma unroll
    for (int c = 0; c < OUTF; c++) s += g_x2[l * OUTF + c] + g_x2[r * OUTF + c];
    sm[t] = s;
    __syncthreads();
    float mx = -1e30f;
    for (int j = 0; j < NB; j++) mx = fmaxf(mx, sm[j]);
    float e = __expf(s - mx);
    __syncthreads();
    sm[t] = e;
    __syncthreads();
    float sum = 0.f;
    for (int j = 0; j < NB; j++) sum += sm[j];
    out[t] = e / sum;
}

// ------------------------------ launch ---------------------------------------
extern "C" void kernel_launch(void* const* d_in, const int* in_sizes, int n_in,
                              void* d_out, int out_size) {
    const float* x   = (const float*)d_in[0];
    const int*   ei  = (const int*)d_in[1];
    const int*   lf  = (const int*)d_in[2];
    const int*   rt  = (const int*)d_in[3];
    const float* W1  = (const float*)d_in[4];
    const float* as1 = (const float*)d_in[5];
    const float* ad1 = (const float*)d_in[6];
    const float* b1  = (const float*)d_in[7];
    const float* W2  = (const float*)d_in[8];
    const float* as2 = (const float*)d_in[9];
    const float* ad2 = (const float*)d_in[10];
    const float* b2  = (const float*)d_in[11];
    float* out = (float*)d_out;

    cudaFuncSetAttribute(gemm1_mma, cudaFuncAttributeMaxDynamicSharedMemorySize,
                         GEMM1_SMEM);
    cudaFuncSetAttribute(gemm2_mma, cudaFuncAttributeMaxDynamicSharedMemorySize,
                         GEMM2_SMEM);

    void *p_xf, *p_w1h, *p_w2h;
    void *p_h1, *p_h2p, *p_x1;
    cudaGetSymbolAddress(&p_xf, g_xf);
    cudaGetSymbolAddress(&p_w1h, g_w1h);
    cudaGetSymbolAddress(&p_w2h, g_w2h);
    cudaGetSymbolAddress(&p_h1, g_h1);
    cudaGetSymbolAddress(&p_h2p, g_h2p);
    cudaGetSymbolAddress(&p_x1, g_x1);

    // fused input conversions (x4 vectorized) + edge counting
    k_prep<<<(NPREP + 255) / 256, 256>>>(x, W1, W2, ei);

    // CSR by destination (scan adds self-loops, resets counts)
    k_scan<<<1, 1024>>>();
    k_scatter<<<(ETOT + 255) / 256, 256>>>(ei);

    // layer 1: h1 = x @ W1^T (fp16 out) + fused alpha1
    gemm1_mma<<<dim3(F1 / 128, N_NODES / 128), 256, GEMM1_SMEM>>>(
        (const __half*)p_xf, (const __half*)p_w1h, (__half*)p_h1, as1, ad1);
    k_agg1<<<N_NODES, 256>>>(b1);

    // layer 2: h2 = x1 @ W2^T, split-K x4 + fused reduce/alpha2
    gemm2_mma<<<dim3(1, N_NODES / 128, KSPLIT), 256, GEMM2_SMEM>>>(
        (const __half*)p_x1, (const __half*)p_w2h, (float*)p_h2p);
    k_reduce_alpha2<<<N_NODES, 160>>>(as2, ad2);
    k_agg2<<<N_NODES, 192>>>(b2);

    // bonds
    k_score<<<1, NB>>>(lf, rt, out);
}